// round 16
// baseline (speedup 1.0000x reference)
#include <cuda_runtime.h>
#include <cuda_fp16.h>
#include <math.h>
#include <stdint.h>

#define NB    512
#define DF    256
#define DZTOT 512
#define KF    512            // 2*DF   halfs (concat [s^2, s], pair-permuted)
#define KZ    1024           // 2*DZTOT
#define BM    128
#define BN    64
#define BK    32             // halfs per stage
#define NSTG  4              // KCH 128 / BK 32
#define KCH   128
#define SPLITF 4
#define SPLITZ 8
#define LOG_2PI 1.8378770664093453f

// smem (uint32 units): Ahi[128][24], Alo, Bhi[64][24], Blo ; data = 16 u32/row
#define ASTRU 24
#define U_AHI 0
#define U_ALO 3072           // 128*24
#define U_BHI 6144
#define U_BLO 7680           // +64*24
#define U_STAGE 9216
#define SMEM_DYN (2*U_STAGE*4)   // 73728 B -> 3 CTAs/SM

// ---------------- scratch ----------------
__device__ uint32_t g_Xfh[NB*KF/2];
__device__ uint32_t g_Xfl[NB*KF/2];
__device__ uint32_t g_Wfh[NB*KF/2];
__device__ uint32_t g_Wfl[NB*KF/2];
__device__ uint32_t g_Xzh[NB*KZ/2];
__device__ uint32_t g_Xzl[NB*KZ/2];
__device__ uint32_t g_Wzh[NB*KZ/2];
__device__ uint32_t g_Wzl[NB*KZ/2];
__device__ float g_Af[NB];
__device__ float g_Az[NB];
__device__ float g_Pf[SPLITF*NB*NB];
__device__ float g_Pz[SPLITZ*NB*NB];
__device__ float g_lse[3*NB];
__device__ int   g_ctr;

__device__ __forceinline__ uint32_t smem_u32(const void* p){
    uint32_t a; asm("{ .reg .u64 t; cvta.to.shared.u64 t, %1; cvt.u32.u64 %0, t; }" : "=r"(a) : "l"(p)); return a;
}
__device__ __forceinline__ void cp16(uint32_t dst, const void* src){
    asm volatile("cp.async.cg.shared.global [%0], [%1], 16;" :: "r"(dst), "l"(src));
}
__device__ __forceinline__ void mma16(float* d, uint32_t a0, uint32_t a1, uint32_t a2, uint32_t a3,
                                      uint32_t b0, uint32_t b1){
    asm("mma.sync.aligned.m16n8k16.row.col.f32.f16.f16.f32 "
        "{%0,%1,%2,%3}, {%4,%5,%6,%7}, {%8,%9}, {%0,%1,%2,%3};"
        : "+f"(d[0]), "+f"(d[1]), "+f"(d[2]), "+f"(d[3])
        : "r"(a0), "r"(a1), "r"(a2), "r"(a3), "r"(b0), "r"(b1));
}

// pair-level permutation: fragment pairs (pair c, pair c+4) become adjacent u32s
__device__ __forceinline__ int pmap(int p){
    return (p & ~7) | ((p & 3) << 1) | ((p >> 2) & 1);
}

// pack two fp32 values into hi/lo __half2 words
__device__ __forceinline__ void hsplit2(float x0, float x1, uint32_t& hu, uint32_t& lu){
    __half h0 = __float2half_rn(x0);
    __half h1 = __float2half_rn(x1);
    __half l0 = __float2half_rn(x0 - __half2float(h0));
    __half l1 = __float2half_rn(x1 - __half2float(h1));
    __half2 hh = __halves2half2(h0, h1);
    __half2 ll = __halves2half2(l0, l1);
    hu = *reinterpret_cast<uint32_t*>(&hh);
    lu = *reinterpret_cast<uint32_t*>(&ll);
}

// ---------------- 1) factorize + fp16 hi/lo split (pair-granular) --------
// log_q[i,j] = A_j + dot(X_i, W_j);  X=[s^2, s], W=[-0.5*iv, m*iv]
__global__ void prep_kernel(const float* __restrict__ f_mean,
                            const float* __restrict__ f_logvar,
                            const float* __restrict__ f_sample,
                            const float* __restrict__ z_mean,
                            const float* __restrict__ z_logvar,
                            const float* __restrict__ z_sample) {
    int j = blockIdx.x;
    int t = threadIdx.x;          // 128 threads, one k-pair per region
    __shared__ float sm[4];
    float part = 0.f;

    if (blockIdx.y == 0) {
        float2 lv = *(const float2*)&f_logvar[j*DF + 2*t];
        float2 m  = *(const float2*)&f_mean  [j*DF + 2*t];
        float2 s  = *(const float2*)&f_sample[j*DF + 2*t];
        float iv0 = __expf(-lv.x), iv1 = __expf(-lv.y);
        int p0 = pmap(t);          // s^2 / -iv/2 region
        int p1 = pmap(128 + t);    // s / m*iv region
        uint32_t hu, lu;
        hsplit2(s.x*s.x,    s.y*s.y,    hu, lu); g_Xfh[j*256 + p0] = hu; g_Xfl[j*256 + p0] = lu;
        hsplit2(s.x,        s.y,        hu, lu); g_Xfh[j*256 + p1] = hu; g_Xfl[j*256 + p1] = lu;
        hsplit2(-0.5f*iv0,  -0.5f*iv1,  hu, lu); g_Wfh[j*256 + p0] = hu; g_Wfl[j*256 + p0] = lu;
        hsplit2(m.x*iv0,    m.y*iv1,    hu, lu); g_Wfh[j*256 + p1] = hu; g_Wfl[j*256 + p1] = lu;
        part = (lv.x + m.x*m.x*iv0) + (lv.y + m.y*m.y*iv1);
    } else {
        #pragma unroll
        for (int it = 0; it < 2; it++) {
            int pd = t + 128*it;              // pair index within d-region (0..255)
            float2 lv = *(const float2*)&z_logvar[j*DZTOT + 2*pd];
            float2 m  = *(const float2*)&z_mean  [j*DZTOT + 2*pd];
            float2 s  = *(const float2*)&z_sample[j*DZTOT + 2*pd];
            float iv0 = __expf(-lv.x), iv1 = __expf(-lv.y);
            int p0 = pmap(pd);
            int p1 = pmap(256 + pd);
            uint32_t hu, lu;
            hsplit2(s.x*s.x,   s.y*s.y,   hu, lu); g_Xzh[j*512 + p0] = hu; g_Xzl[j*512 + p0] = lu;
            hsplit2(s.x,       s.y,       hu, lu); g_Xzh[j*512 + p1] = hu; g_Xzl[j*512 + p1] = lu;
            hsplit2(-0.5f*iv0, -0.5f*iv1, hu, lu); g_Wzh[j*512 + p0] = hu; g_Wzl[j*512 + p0] = lu;
            hsplit2(m.x*iv0,   m.y*iv1,   hu, lu); g_Wzh[j*512 + p1] = hu; g_Wzl[j*512 + p1] = lu;
            part += (lv.x + m.x*m.x*iv0) + (lv.y + m.y*m.y*iv1);
        }
    }
    #pragma unroll
    for (int o = 16; o; o >>= 1) part += __shfl_xor_sync(0xffffffffu, part, o);
    if ((t & 31) == 0) sm[t >> 5] = part;
    __syncthreads();
    if (t == 0) {
        float r = (sm[0] + sm[1]) + (sm[2] + sm[3]);
        float D = (blockIdx.y == 0) ? (float)DF : (float)DZTOT;
        float A = -0.5f*(D*LOG_2PI + r);
        if (blockIdx.y == 0) g_Af[j] = A; else g_Az[j] = A;
    }
}

// ---------------- 2) fp16 hi/lo mma.sync NT-GEMM -------------------------
// 384 identical CTAs of 128x64xK128. D += Ah*Bh + Al*Bh + Ah*Bl (fp32 acc).
__global__ void __launch_bounds__(256, 3) gemm_mma_kernel() {
    extern __shared__ uint32_t dsm[];
    uint32_t sbase = smem_u32(dsm);

    int t    = threadIdx.x;
    int lane = t & 31;
    int wid  = t >> 5;
    int wm   = wid >> 1;          // 0..3 -> 32-row slab
    int wn   = wid & 1;           // 0..1 -> 32-col slab
    int g    = lane >> 2;
    int c    = lane & 3;

    // block mapping: [0,128) f split4 ; [128,384) z split8 — uniform K128
    int b = blockIdx.x;
    const uint32_t* __restrict__ Xh;
    const uint32_t* __restrict__ Xl;
    const uint32_t* __restrict__ Wh;
    const uint32_t* __restrict__ Wl;
    float* __restrict__ P;
    int Ku, kOffU, tile;
    if (b < SPLITF*32) {
        int s = b >> 5; tile = b & 31;
        Xh = g_Xfh; Xl = g_Xfl; Wh = g_Wfh; Wl = g_Wfl;
        P = g_Pf + s*(NB*NB); Ku = KF/2; kOffU = s*(KCH/2);
    } else {
        b -= SPLITF*32;
        int s = b >> 5; tile = b & 31;
        Xh = g_Xzh; Xl = g_Xzl; Wh = g_Wzh; Wl = g_Wzl;
        P = g_Pz + s*(NB*NB); Ku = KZ/2; kOffU = s*(KCH/2);
    }
    int rowBase = (tile >> 3) * BM;
    int colBase = (tile & 7) * BN;

    const uint32_t* Xhb = Xh + rowBase*Ku + kOffU;
    const uint32_t* Xlb = Xl + rowBase*Ku + kOffU;
    const uint32_t* Whb = Wh + colBase*Ku + kOffU;
    const uint32_t* Wlb = Wl + colBase*Ku + kOffU;

    auto issue = [&](int kt, int s){
        uint32_t sb = sbase + s*(U_STAGE*4);
        int kb = kt*16;                          // u32 offset in row
        #pragma unroll
        for (int i = 0; i < 2; i++) {            // A: 512 chunks of 16B
            int id = t + 256*i, r = id >> 2, cc = id & 3;
            cp16(sb + (U_AHI + r*ASTRU + cc*4)*4, Xhb + r*Ku + kb + cc*4);
            cp16(sb + (U_ALO + r*ASTRU + cc*4)*4, Xlb + r*Ku + kb + cc*4);
        }
        {                                        // B: 256 chunks
            int r = t >> 2, cc = t & 3;
            cp16(sb + (U_BHI + r*ASTRU + cc*4)*4, Whb + r*Ku + kb + cc*4);
            cp16(sb + (U_BLO + r*ASTRU + cc*4)*4, Wlb + r*Ku + kb + cc*4);
        }
        asm volatile("cp.async.commit_group;" ::: "memory");
    };

    float acc[2][4][4] = {};

    auto compute = [&](int s){
        const uint32_t* st = dsm + s*U_STAGE;
        #pragma unroll
        for (int g8 = 0; g8 < 2; g8++) {
            int ko = g8*8 + 2*c;
            uint2 AH[2][2], BH[4], AX[2][2];
            #pragma unroll
            for (int ma = 0; ma < 2; ma++) {
                int r0 = (wm*32 + ma*16 + g)*ASTRU + ko;
                AH[ma][0] = *(const uint2*)&st[U_AHI + r0];
                AH[ma][1] = *(const uint2*)&st[U_AHI + r0 + 8*ASTRU];
            }
            #pragma unroll
            for (int nb = 0; nb < 4; nb++)
                BH[nb] = *(const uint2*)&st[U_BHI + (wn*32 + nb*8 + g)*ASTRU + ko];
            #pragma unroll
            for (int ma = 0; ma < 2; ma++)
                #pragma unroll
                for (int nb = 0; nb < 4; nb++)
                    mma16(acc[ma][nb], AH[ma][0].x, AH[ma][1].x, AH[ma][0].y, AH[ma][1].y,
                          BH[nb].x, BH[nb].y);
            // A-lo pass
            #pragma unroll
            for (int ma = 0; ma < 2; ma++) {
                int r0 = (wm*32 + ma*16 + g)*ASTRU + ko;
                AX[ma][0] = *(const uint2*)&st[U_ALO + r0];
                AX[ma][1] = *(const uint2*)&st[U_ALO + r0 + 8*ASTRU];
            }
            #pragma unroll
            for (int ma = 0; ma < 2; ma++)
                #pragma unroll
                for (int nb = 0; nb < 4; nb++)
                    mma16(acc[ma][nb], AX[ma][0].x, AX[ma][1].x, AX[ma][0].y, AX[ma][1].y,
                          BH[nb].x, BH[nb].y);
            // B-lo pass (reuse BH regs)
            #pragma unroll
            for (int nb = 0; nb < 4; nb++)
                BH[nb] = *(const uint2*)&st[U_BLO + (wn*32 + nb*8 + g)*ASTRU + ko];
            #pragma unroll
            for (int ma = 0; ma < 2; ma++)
                #pragma unroll
                for (int nb = 0; nb < 4; nb++)
                    mma16(acc[ma][nb], AH[ma][0].x, AH[ma][1].x, AH[ma][0].y, AH[ma][1].y,
                          BH[nb].x, BH[nb].y);
        }
    };

    // single-sync pipeline: wait -> sync -> issue(next) -> compute(cur)
    issue(0, 0);
    for (int kt = 0; kt < NSTG; kt++) {
        int s = kt & 1;
        asm volatile("cp.async.wait_group 0;" ::: "memory");
        __syncthreads();
        if (kt + 1 < NSTG) issue(kt + 1, s ^ 1);
        compute(s);
    }

    #pragma unroll
    for (int ma = 0; ma < 2; ma++) {
        int i0 = rowBase + wm*32 + ma*16 + g;
        #pragma unroll
        for (int nb = 0; nb < 4; nb++) {
            int j0 = colBase + wn*32 + nb*8 + 2*c;
            *(float2*)&P[ i0   *NB + j0] = make_float2(acc[ma][nb][0], acc[ma][nb][1]);
            *(float2*)&P[(i0+8)*NB + j0] = make_float2(acc[ma][nb][2], acc[ma][nb][3]);
        }
    }
}

// ---------------- 3) per-row LSE (warp-per-row) + fused final ------------
__device__ __forceinline__ float wred_max(float v){
    #pragma unroll
    for (int o = 16; o; o >>= 1) v = fmaxf(v, __shfl_xor_sync(0xffffffffu, v, o));
    return v;
}
__device__ __forceinline__ float wred_sum(float v){
    #pragma unroll
    for (int o = 16; o; o >>= 1) v += __shfl_xor_sync(0xffffffffu, v, o);
    return v;
}
__device__ __forceinline__ float bred_sum(float v, float* sm, int t) {
    #pragma unroll
    for (int o = 16; o; o >>= 1) v += __shfl_xor_sync(0xffffffffu, v, o);
    if ((t & 31) == 0) sm[t >> 5] = v;
    __syncthreads();
    v = (sm[0] + sm[1]) + (sm[2] + sm[3]);
    __syncthreads();
    return v;
}

__global__ void lse_kernel(const int* __restrict__ num_train_p,
                           float* __restrict__ out, int out_size) {
    int t = threadIdx.x;              // 128 threads = 4 warps; warp owns a row
    int lane = t & 31, w = t >> 5;
    int i = blockIdx.x*4 + w;
    __shared__ float sm[4];
    __shared__ bool isLast;

    float a[16], bb[16];
    #pragma unroll
    for (int q = 0; q < 4; q++) {
        int j4 = q*128 + lane*4;
        float4 va = *(const float4*)&g_Af[j4];
        float4 vz = *(const float4*)&g_Az[j4];
        float a0 = va.x, a1 = va.y, a2 = va.z, a3 = va.w;
        float b0 = vz.x, b1 = vz.y, b2 = vz.z, b3 = vz.w;
        #pragma unroll
        for (int s = 0; s < SPLITF; s++) {
            float4 v = *(const float4*)&g_Pf[s*(NB*NB) + i*NB + j4];
            a0 += v.x; a1 += v.y; a2 += v.z; a3 += v.w;
        }
        #pragma unroll
        for (int s = 0; s < SPLITZ; s++) {
            float4 v = *(const float4*)&g_Pz[s*(NB*NB) + i*NB + j4];
            b0 += v.x; b1 += v.y; b2 += v.z; b3 += v.w;
        }
        a[q*4+0] = a0; a[q*4+1] = a1; a[q*4+2] = a2; a[q*4+3] = a3;
        bb[q*4+0] = b0; bb[q*4+1] = b1; bb[q*4+2] = b2; bb[q*4+3] = b3;
    }

    float ma = -1e30f, mb = -1e30f, mc = -1e30f;
    #pragma unroll
    for (int k = 0; k < 16; k++) {
        ma = fmaxf(ma, a[k]);
        mb = fmaxf(mb, bb[k]);
        mc = fmaxf(mc, a[k] + bb[k]);
    }
    float Ma = wred_max(ma), Mb = wred_max(mb), Mc = wred_max(mc);

    float sa = 0.f, sb = 0.f, sc = 0.f;
    #pragma unroll
    for (int k = 0; k < 16; k++) {
        sa += __expf(a[k] - Ma);
        sb += __expf(bb[k] - Mb);
        sc += __expf(a[k] + bb[k] - Mc);
    }
    float Sa = wred_sum(sa), Sb = wred_sum(sb), Sc = wred_sum(sc);

    if (lane == 0) {
        g_lse[0*NB + i] = Ma + logf(Sa);
        g_lse[1*NB + i] = Mb + logf(Sb);
        g_lse[2*NB + i] = Mc + logf(Sc);
    }
    __syncthreads();
    if (t == 0) {
        __threadfence();
        int v = atomicAdd(&g_ctr, 1);
        isLast = (v == (NB/4) - 1);
    }
    __syncthreads();

    if (isLast) {
        float s0 = 0.f, s1 = 0.f, s2 = 0.f;
        #pragma unroll
        for (int r = t; r < NB; r += 128) {
            s0 += g_lse[0*NB + r];
            s1 += g_lse[1*NB + r];
            s2 += g_lse[2*NB + r];
        }
        s0 = bred_sum(s0, sm, t);
        s1 = bred_sum(s1, sm, t);
        s2 = bred_sum(s2, sm, t);
        if (t == 0) {
            g_ctr = 0;
            int v = num_train_p[0];
            float nt;
            if (v > 0 && v < (1 << 30)) nt = (float)v;
            else nt = __int_as_float(v);
            float clogNM = logf(nt * (float)NB);
            float Hf  = -s0 / (float)NB + clogNM;
            float Hz  = -s1 / (float)NB + clogNM;
            float Hfz = -s2 / (float)NB + clogNM;
            float MI  = Hf + Hz - Hfz;
            if (out_size > 0) out[0] = MI;
            if (out_size > 1) out[1] = Hf;
            if (out_size > 2) out[2] = Hz;
            if (out_size > 3) out[3] = Hfz;
        }
    }
}

// ---------------- launch ----------------
extern "C" void kernel_launch(void* const* d_in, const int* in_sizes, int n_in,
                              void* d_out, int out_size) {
    const float* f_mean   = (const float*)d_in[0];
    const float* f_logvar = (const float*)d_in[1];
    const float* f_sample = (const float*)d_in[2];
    const float* z_mean   = (const float*)d_in[3];
    const float* z_logvar = (const float*)d_in[4];
    const float* z_sample = (const float*)d_in[5];
    const int*   num_train = (const int*)d_in[6];

    cudaFuncSetAttribute(gemm_mma_kernel,
                         cudaFuncAttributeMaxDynamicSharedMemorySize, SMEM_DYN);

    prep_kernel<<<dim3(NB, 2), 128>>>(f_mean, f_logvar, f_sample,
                                      z_mean, z_logvar, z_sample);
    gemm_mma_kernel<<<(SPLITF + SPLITZ) * 32, 256, SMEM_DYN>>>();
    lse_kernel<<<NB/4, 128>>>(num_train, (float*)d_out, out_size);
}